// round 12
// baseline (speedup 1.0000x reference)
#include <cuda_runtime.h>

// PS-ROI Pooling, float4-vectorized windowed average.
// features [4,1029,64,64] f32, rois [1024,5] f32, out [1024,21,7,7] f32.
//
// NUMERICS CONTRACT (frozen, validated R10/R11: rel_err 9.5e-7):
//  - bounds: separate __fmul_rn/__fadd_rn, rintf, __fdividef (div.full.f32,
//    the XLA:GPU fast f32 division) for bin = roi/7 and the final s/area.
//  - window sums exact f32 (order-insensitive at this tolerance).
//
// PERF (R12): one output per thread; grid (NUM_ROIS, 5) of 256-thread
// blocks (fine granularity -> balanced waves); __launch_bounds__(256,6)
// to lift occupancy (v11: 53 regs -> 39% occ); nc==1 fast path.

#define BATCH 4
#define POOLED 7
#define OUTPUT_DIM 21
#define CHANNELS (OUTPUT_DIM * POOLED * POOLED)  // 1029
#define H 64
#define W 64
#define SPATIAL_SCALE 0.0625f
#define NUM_ROIS 1024
#define PER_ROI CHANNELS                         // 1029
#define PLANE (H * W)
#define SEGS 5                                   // ceil(1029/256)

__global__ __launch_bounds__(256, 6)
void psroi_v12_kernel(const float* __restrict__ features,
                      const float* __restrict__ rois,
                      float* __restrict__ out)
{
    __shared__ int sh_hs[POOLED], sh_he[POOLED];
    __shared__ int sh_ws[POOLED], sh_we[POOLED];
    __shared__ int sh_b;

    const int n   = blockIdx.x;
    const int tid = threadIdx.x;

    if (tid < 2 * POOLED) {
        const float* r = rois + n * 5;
        const int axis = tid / POOLED;   // 0 -> h (y: r[2],r[4]), 1 -> w (x: r[1],r[3])
        const int p    = tid % POOLED;

        float c_start = axis ? r[1] : r[2];
        float c_end   = axis ? r[3] : r[4];

        float rs = __fmul_rn(rintf(c_start), SPATIAL_SCALE);
        float re = __fmul_rn(rintf(__fadd_rn(c_end, 1.0f)), SPATIAL_SCALE);
        float roi_sz = fmaxf(__fsub_rn(re, rs), 0.1f);
        float bin    = __fdividef(roi_sz, (float)POOLED);   // div.full.f32 (XLA match)

        float fp = (float)p;
        float v0 = __fadd_rn(__fmul_rn(fp, bin), rs);
        float v1 = __fadd_rn(__fmul_rn(__fadd_rn(fp, 1.0f), bin), rs);

        int s = (int)fminf(fmaxf(floorf(v0), 0.0f), 64.0f);
        int e = (int)fminf(fmaxf(ceilf (v1), 0.0f), 64.0f);

        if (axis == 0) { sh_hs[p] = s; sh_he[p] = e; }
        else           { sh_ws[p] = s; sh_we[p] = e; }
        if (tid == 0) sh_b = (int)r[0];
    }
    __syncthreads();

    const int local = blockIdx.y * 256 + tid;
    if (local >= PER_ROI) return;

    const int pw = local % POOLED;
    const int ph = (local / POOLED) % POOLED;

    const int hs = sh_hs[ph], he = sh_he[ph];
    const int ws = sh_ws[pw], we = sh_we[pw];

    // float4 chunk range covering [ws, we) within a 64-float row.
    const int fc = ws >> 2;
    const int lc = (we - 1) >> 2;        // empty window (we<=ws) -> lc < fc possible
    const int nc = lc - fc + 1;

    const float* plane = features + ((size_t)sh_b * CHANNELS + (size_t)local) * PLANE;
    const float4* p4   = (const float4*)plane + fc;

    float s;
    if (nc == 1) {
        // Fast path: single aligned chunk covers the whole row window.
        float mx = (fc*4 + 0 >= ws && fc*4 + 0 < we) ? 1.0f : 0.0f;
        float my = (fc*4 + 1 >= ws && fc*4 + 1 < we) ? 1.0f : 0.0f;
        float mz = (fc*4 + 2 >= ws && fc*4 + 2 < we) ? 1.0f : 0.0f;
        float mw = (fc*4 + 3 >= ws && fc*4 + 3 < we) ? 1.0f : 0.0f;
        float ax = 0.0f, ay = 0.0f, az = 0.0f, aw = 0.0f;
        for (int h = hs; h < he; ++h) {
            float4 v = __ldg(p4 + h * (W / 4));
            ax = fmaf(v.x, mx, ax);
            ay = fmaf(v.y, my, ay);
            az = fmaf(v.z, mz, az);
            aw = fmaf(v.w, mw, aw);
        }
        s = (ax + ay) + (az + aw);
    } else {
        float4 msk[3];
#pragma unroll
        for (int k = 0; k < 3; ++k) {
            int b0 = (fc + k) * 4;
            msk[k].x = (b0 + 0 >= ws && b0 + 0 < we) ? 1.0f : 0.0f;
            msk[k].y = (b0 + 1 >= ws && b0 + 1 < we) ? 1.0f : 0.0f;
            msk[k].z = (b0 + 2 >= ws && b0 + 2 < we) ? 1.0f : 0.0f;
            msk[k].w = (b0 + 3 >= ws && b0 + 3 < we) ? 1.0f : 0.0f;
        }
        float ax = 0.0f, ay = 0.0f, az = 0.0f, aw = 0.0f;
        for (int h = hs; h < he; ++h) {
            const float4* r4 = p4 + h * (W / 4);
#pragma unroll 3
            for (int k = 0; k < nc; ++k) {
                float4 v = __ldg(r4 + k);
                ax = fmaf(v.x, msk[k].x, ax);
                ay = fmaf(v.y, msk[k].y, ay);
                az = fmaf(v.z, msk[k].z, az);
                aw = fmaf(v.w, msk[k].w, aw);
            }
        }
        s = (ax + ay) + (az + aw);
    }

    int area = (he - hs) * (we - ws);
    out[(size_t)n * PER_ROI + local] = (area > 0) ? __fdividef(s, (float)area) : 0.0f;
}

extern "C" void kernel_launch(void* const* d_in, const int* in_sizes, int n_in,
                              void* d_out, int out_size)
{
    const float* features = (const float*)d_in[0];
    const float* rois     = (const float*)d_in[1];
    float* out            = (float*)d_out;

    dim3 grid(NUM_ROIS, SEGS);
    psroi_v12_kernel<<<grid, 256>>>(features, rois, out);
}

// round 13
// speedup vs baseline: 1.0128x; 1.0128x over previous
#include <cuda_runtime.h>

// PS-ROI Pooling, float4-vectorized windowed average, shared-precomputed masks.
// features [4,1029,64,64] f32, rois [1024,5] f32, out [1024,21,7,7] f32.
//
// NUMERICS CONTRACT (frozen, validated R10-R12: rel_err 9.5e-7):
//  - bounds: separate __fmul_rn/__fadd_rn, rintf, __fdividef (div.full.f32,
//    XLA:GPU's fast f32 division) for bin = roi/7 and final s/area.
//  - window sums exact f32.
//
// PERF (R13): v12 showed alu=40.6% -- half the instruction stream was
// per-output mask/index arithmetic. Masks depend only on pw (7 values) and
// h-bounds only on ph (7 values): precompute ONCE per ROI into shared.
// Inner loop per output = 2 IMADs + LDS + pure LDG.128/FFMA chain.

#define BATCH 4
#define POOLED 7
#define OUTPUT_DIM 21
#define CHANNELS (OUTPUT_DIM * POOLED * POOLED)  // 1029
#define H 64
#define W 64
#define SPATIAL_SCALE 0.0625f
#define NUM_ROIS 1024
#define PER_ROI CHANNELS                         // 1029
#define PLANE (H * W)

__global__ __launch_bounds__(256, 6)
void psroi_v13_kernel(const float* __restrict__ features,
                      const float* __restrict__ rois,
                      float* __restrict__ out)
{
    __shared__ int    sh_hs[POOLED], sh_he[POOLED];
    __shared__ int    sh_fc[POOLED], sh_nc[POOLED];
    __shared__ float  sh_area_h[POOLED], sh_area_w[POOLED];  // (he-hs), (we-ws) as float
    __shared__ float4 sh_msk[POOLED][3];
    __shared__ int    sh_b;

    const int n   = blockIdx.x;
    const int tid = threadIdx.x;

    if (tid < 2 * POOLED) {
        const float* r = rois + n * 5;
        const int axis = tid / POOLED;   // 0 -> h (y: r[2],r[4]), 1 -> w (x: r[1],r[3])
        const int p    = tid % POOLED;

        float c_start = axis ? r[1] : r[2];
        float c_end   = axis ? r[3] : r[4];

        float rs = __fmul_rn(rintf(c_start), SPATIAL_SCALE);
        float re = __fmul_rn(rintf(__fadd_rn(c_end, 1.0f)), SPATIAL_SCALE);
        float roi_sz = fmaxf(__fsub_rn(re, rs), 0.1f);
        float bin    = __fdividef(roi_sz, (float)POOLED);   // div.full.f32 (XLA match)

        float fp = (float)p;
        float v0 = __fadd_rn(__fmul_rn(fp, bin), rs);
        float v1 = __fadd_rn(__fmul_rn(__fadd_rn(fp, 1.0f), bin), rs);

        int s = (int)fminf(fmaxf(floorf(v0), 0.0f), 64.0f);
        int e = (int)fminf(fmaxf(ceilf (v1), 0.0f), 64.0f);

        if (axis == 0) {
            sh_hs[p] = s; sh_he[p] = e;
            sh_area_h[p] = (float)(e - s);
        } else {
            int fc = s >> 2;
            int lc = (e - 1) >> 2;            // empty -> lc < fc
            sh_fc[p] = fc;
            sh_nc[p] = lc - fc + 1;
            sh_area_w[p] = (float)(e - s);
#pragma unroll
            for (int k = 0; k < 3; ++k) {
                int b0 = (fc + k) * 4;
                float4 m;
                m.x = (b0 + 0 >= s && b0 + 0 < e) ? 1.0f : 0.0f;
                m.y = (b0 + 1 >= s && b0 + 1 < e) ? 1.0f : 0.0f;
                m.z = (b0 + 2 >= s && b0 + 2 < e) ? 1.0f : 0.0f;
                m.w = (b0 + 3 >= s && b0 + 3 < e) ? 1.0f : 0.0f;
                sh_msk[p][k] = m;
            }
        }
        if (tid == 0) sh_b = (int)r[0];
    }
    __syncthreads();

    const float* base = features + (size_t)sh_b * CHANNELS * PLANE;
    float* out_roi = out + (size_t)n * PER_ROI;

    for (int local = tid; local < PER_ROI; local += 256) {
        const int pw = local % POOLED;
        const int ph = (local / POOLED) % POOLED;

        const int hs = sh_hs[ph], he = sh_he[ph];
        const int fc = sh_fc[pw], nc = sh_nc[pw];

        const float4* p4 = (const float4*)(base + (size_t)local * PLANE) + fc;

        float4 m0 = sh_msk[pw][0];
        float ax = 0.0f, ay = 0.0f, az = 0.0f, aw = 0.0f;

        if (nc == 1) {
            for (int h = hs; h < he; ++h) {
                float4 v = __ldg(p4 + h * (W / 4));
                ax = fmaf(v.x, m0.x, ax);
                ay = fmaf(v.y, m0.y, ay);
                az = fmaf(v.z, m0.z, az);
                aw = fmaf(v.w, m0.w, aw);
            }
        } else {
            float4 m1 = sh_msk[pw][1];
            float4 m2 = sh_msk[pw][2];
            for (int h = hs; h < he; ++h) {
                const float4* r4 = p4 + h * (W / 4);
                float4 v0 = __ldg(r4);
                float4 v1 = __ldg(r4 + 1);
                ax = fmaf(v0.x, m0.x, ax);
                ay = fmaf(v0.y, m0.y, ay);
                az = fmaf(v0.z, m0.z, az);
                aw = fmaf(v0.w, m0.w, aw);
                ax = fmaf(v1.x, m1.x, ax);
                ay = fmaf(v1.y, m1.y, ay);
                az = fmaf(v1.z, m1.z, az);
                aw = fmaf(v1.w, m1.w, aw);
                if (nc > 2) {
                    float4 v2 = __ldg(r4 + 2);
                    ax = fmaf(v2.x, m2.x, ax);
                    ay = fmaf(v2.y, m2.y, ay);
                    az = fmaf(v2.z, m2.z, az);
                    aw = fmaf(v2.w, m2.w, aw);
                }
            }
        }
        float s = (ax + ay) + (az + aw);

        float area = sh_area_h[ph] * sh_area_w[pw];
        out_roi[local] = (area > 0.0f) ? __fdividef(s, area) : 0.0f;
    }
}

extern "C" void kernel_launch(void* const* d_in, const int* in_sizes, int n_in,
                              void* d_out, int out_size)
{
    const float* features = (const float*)d_in[0];
    const float* rois     = (const float*)d_in[1];
    float* out            = (float*)d_out;

    psroi_v13_kernel<<<NUM_ROIS, 256>>>(features, rois, out);
}

// round 14
// speedup vs baseline: 1.2000x; 1.1848x over previous
#include <cuda_runtime.h>

// PS-ROI Pooling, float4 windows, shared masks, h-unroll-2 for MLP.
// features [4,1029,64,64] f32, rois [1024,5] f32, out [1024,21,7,7] f32.
//
// NUMERICS CONTRACT (frozen, validated R10-R13: rel_err 9.5e-7):
//  - bounds: separate __fmul_rn/__fadd_rn, rintf, __fdividef (div.full.f32,
//    XLA:GPU's fast f32 division) for bin = roi/7 and final s/area.
//  - window sums exact f32 (order-insensitive at this tolerance).
//
// PERF (R14): v13 profile = latency-bound, ~1.3 loads in flight per warp
// (variable-trip h loop serializes issue). Fix: unroll h by 2 with dual
// accumulator banks (2-4 independent LDG.128 in flight), split each ROI
// across 2 blocks to smooth the wave tail (2048 blocks vs 888 concurrent).

#define BATCH 4
#define POOLED 7
#define OUTPUT_DIM 21
#define CHANNELS (OUTPUT_DIM * POOLED * POOLED)  // 1029
#define H 64
#define W 64
#define SPATIAL_SCALE 0.0625f
#define NUM_ROIS 1024
#define PER_ROI CHANNELS                         // 1029
#define PLANE (H * W)
#define ROWQ (W / 4)                             // 16 float4 per row

__global__ __launch_bounds__(256, 5)
void psroi_v14_kernel(const float* __restrict__ features,
                      const float* __restrict__ rois,
                      float* __restrict__ out)
{
    __shared__ int    sh_hs[POOLED], sh_he[POOLED];
    __shared__ int    sh_fc[POOLED], sh_nc[POOLED];
    __shared__ float  sh_area_h[POOLED], sh_area_w[POOLED];
    __shared__ float4 sh_msk[POOLED][3];
    __shared__ int    sh_b;

    const int n   = blockIdx.x;
    const int tid = threadIdx.x;

    if (tid < 2 * POOLED) {
        const float* r = rois + n * 5;
        const int axis = tid / POOLED;   // 0 -> h (y: r[2],r[4]), 1 -> w (x: r[1],r[3])
        const int p    = tid % POOLED;

        float c_start = axis ? r[1] : r[2];
        float c_end   = axis ? r[3] : r[4];

        float rs = __fmul_rn(rintf(c_start), SPATIAL_SCALE);
        float re = __fmul_rn(rintf(__fadd_rn(c_end, 1.0f)), SPATIAL_SCALE);
        float roi_sz = fmaxf(__fsub_rn(re, rs), 0.1f);
        float bin    = __fdividef(roi_sz, (float)POOLED);   // div.full.f32 (XLA match)

        float fp = (float)p;
        float v0 = __fadd_rn(__fmul_rn(fp, bin), rs);
        float v1 = __fadd_rn(__fmul_rn(__fadd_rn(fp, 1.0f), bin), rs);

        int s = (int)fminf(fmaxf(floorf(v0), 0.0f), 64.0f);
        int e = (int)fminf(fmaxf(ceilf (v1), 0.0f), 64.0f);

        if (axis == 0) {
            sh_hs[p] = s; sh_he[p] = e;
            sh_area_h[p] = (float)(e - s);
        } else {
            int fc = s >> 2;
            int lc = (e - 1) >> 2;            // empty -> lc < fc
            sh_fc[p] = fc;
            sh_nc[p] = lc - fc + 1;
            sh_area_w[p] = (float)(e - s);
#pragma unroll
            for (int k = 0; k < 3; ++k) {
                int b0 = (fc + k) * 4;
                float4 m;
                m.x = (b0 + 0 >= s && b0 + 0 < e) ? 1.0f : 0.0f;
                m.y = (b0 + 1 >= s && b0 + 1 < e) ? 1.0f : 0.0f;
                m.z = (b0 + 2 >= s && b0 + 2 < e) ? 1.0f : 0.0f;
                m.w = (b0 + 3 >= s && b0 + 3 < e) ? 1.0f : 0.0f;
                sh_msk[p][k] = m;
            }
        }
        if (tid == 0) sh_b = (int)r[0];
    }
    __syncthreads();

    const float* base = features + (size_t)sh_b * CHANNELS * PLANE;
    float* out_roi = out + (size_t)n * PER_ROI;

    // Segment of this ROI's 1029 outputs handled by this block (y = 0 or 1).
    const int seg_start = blockIdx.y * 515;
    const int seg_end   = blockIdx.y ? PER_ROI : 515;

    for (int local = seg_start + tid; local < seg_end; local += 256) {
        const int pw = local % POOLED;
        const int ph = (local / POOLED) % POOLED;

        const int hs = sh_hs[ph], he = sh_he[ph];
        const int fc = sh_fc[pw], nc = sh_nc[pw];

        const float4* p4 = (const float4*)(base + (size_t)local * PLANE) + fc;

        float4 m0 = sh_msk[pw][0];
        float ax = 0.0f, ay = 0.0f, az = 0.0f, aw = 0.0f;   // bank A (even rows)
        float bx = 0.0f, by = 0.0f, bz = 0.0f, bw = 0.0f;   // bank B (odd rows)

        if (nc == 1) {
            int h = hs;
            for (; h + 2 <= he; h += 2) {
                float4 v0 = __ldg(p4 + h * ROWQ);
                float4 v1 = __ldg(p4 + (h + 1) * ROWQ);
                ax = fmaf(v0.x, m0.x, ax);
                ay = fmaf(v0.y, m0.y, ay);
                az = fmaf(v0.z, m0.z, az);
                aw = fmaf(v0.w, m0.w, aw);
                bx = fmaf(v1.x, m0.x, bx);
                by = fmaf(v1.y, m0.y, by);
                bz = fmaf(v1.z, m0.z, bz);
                bw = fmaf(v1.w, m0.w, bw);
            }
            if (h < he) {
                float4 v = __ldg(p4 + h * ROWQ);
                ax = fmaf(v.x, m0.x, ax);
                ay = fmaf(v.y, m0.y, ay);
                az = fmaf(v.z, m0.z, az);
                aw = fmaf(v.w, m0.w, aw);
            }
        } else if (nc == 2) {
            float4 m1 = sh_msk[pw][1];
            int h = hs;
            for (; h + 2 <= he; h += 2) {
                const float4* r0 = p4 + h * ROWQ;
                const float4* r1 = p4 + (h + 1) * ROWQ;
                float4 v00 = __ldg(r0);
                float4 v01 = __ldg(r0 + 1);
                float4 v10 = __ldg(r1);
                float4 v11 = __ldg(r1 + 1);
                ax = fmaf(v00.x, m0.x, ax);
                ay = fmaf(v00.y, m0.y, ay);
                az = fmaf(v00.z, m0.z, az);
                aw = fmaf(v00.w, m0.w, aw);
                bx = fmaf(v01.x, m1.x, bx);
                by = fmaf(v01.y, m1.y, by);
                bz = fmaf(v01.z, m1.z, bz);
                bw = fmaf(v01.w, m1.w, bw);
                ax = fmaf(v10.x, m0.x, ax);
                ay = fmaf(v10.y, m0.y, ay);
                az = fmaf(v10.z, m0.z, az);
                aw = fmaf(v10.w, m0.w, aw);
                bx = fmaf(v11.x, m1.x, bx);
                by = fmaf(v11.y, m1.y, by);
                bz = fmaf(v11.z, m1.z, bz);
                bw = fmaf(v11.w, m1.w, bw);
            }
            if (h < he) {
                const float4* r0 = p4 + h * ROWQ;
                float4 v00 = __ldg(r0);
                float4 v01 = __ldg(r0 + 1);
                ax = fmaf(v00.x, m0.x, ax);
                ay = fmaf(v00.y, m0.y, ay);
                az = fmaf(v00.z, m0.z, az);
                aw = fmaf(v00.w, m0.w, aw);
                bx = fmaf(v01.x, m1.x, bx);
                by = fmaf(v01.y, m1.y, by);
                bz = fmaf(v01.z, m1.z, bz);
                bw = fmaf(v01.w, m1.w, bw);
            }
        } else {
            // nc == 3 (rare) — dynamic chunk loop, rows unrolled implicitly.
            float4 m1 = sh_msk[pw][1];
            float4 m2 = sh_msk[pw][2];
            for (int h = hs; h < he; ++h) {
                const float4* r4 = p4 + h * ROWQ;
                float4 v0 = __ldg(r4);
                float4 v1 = __ldg(r4 + 1);
                float4 v2 = __ldg(r4 + 2);
                ax = fmaf(v0.x, m0.x, ax);
                ay = fmaf(v0.y, m0.y, ay);
                az = fmaf(v0.z, m0.z, az);
                aw = fmaf(v0.w, m0.w, aw);
                bx = fmaf(v1.x, m1.x, bx);
                by = fmaf(v1.y, m1.y, by);
                bz = fmaf(v1.z, m1.z, bz);
                bw = fmaf(v1.w, m1.w, bw);
                ax = fmaf(v2.x, m2.x, ax);
                ay = fmaf(v2.y, m2.y, ay);
                az = fmaf(v2.z, m2.z, az);
                aw = fmaf(v2.w, m2.w, aw);
            }
        }

        float s = ((ax + bx) + (ay + by)) + ((az + bz) + (aw + bw));

        float area = sh_area_h[ph] * sh_area_w[pw];
        out_roi[local] = (area > 0.0f) ? __fdividef(s, area) : 0.0f;
    }
}

extern "C" void kernel_launch(void* const* d_in, const int* in_sizes, int n_in,
                              void* d_out, int out_size)
{
    const float* features = (const float*)d_in[0];
    const float* rois     = (const float*)d_in[1];
    float* out            = (float*)d_out;

    dim3 grid(NUM_ROIS, 2);
    psroi_v14_kernel<<<grid, 256>>>(features, rois, out);
}